// round 12
// baseline (speedup 1.0000x reference)
#include <cuda_runtime.h>
#include <cuda_fp16.h>
#include <cstdint>

// GCN: out = spmm(A, relu(spmm(A, x@W1)+b1) @ W2) + b2
// N=50000, E=1.6M, 512 -> 128 -> 64.
// GEMM1: mma.sync tf32 (rn) -> S1 fp16. GEMM2: fp32 FFMA -> S2 fp16.
// SpMM: on-device CSR (int2 {col,w}) + warp-per-row, fp16 gather payload.
// Overlap: CSR build || GEMM1, and GEMM2(half0) || spmm1(half1).
// edge_index is int32 on device (JAX default config downcasts int64).

#define IN_DIM  512
#define HID_DIM 128
#define OUT_DIM 64
#define N_MAX   50000
#define E_MAX   1600000

__device__ __half g_S1[(size_t)N_MAX * HID_DIM];  // x @ W1        (fp16)
__device__ float  g_H [(size_t)N_MAX * HID_DIM];  // spmm1 out +b1 (fp32)
__device__ __half g_S2[(size_t)N_MAX * OUT_DIM];  // relu(H) @ W2  (fp16)

// CSR scratch
__device__ int  g_rowptr[N_MAX + 1];
__device__ int  g_rowaux[N_MAX];      // counts, then scatter cursors
__device__ int2 g_edges [E_MAX];      // {colidx, weight-as-int}

// ---------------------------------------------------------------------------
__device__ __forceinline__ float to_tf32_rn(float f) {
    uint32_t o;
    asm("cvt.rn.tf32.f32 %0, %1;" : "=r"(o) : "f"(f));
    return __uint_as_float(o);
}

// ---------------------------------------------------------------------------
// GEMM1: S1[M,128] = A[M,512] @ W[512,128] via mma.sync.m16n8k8 tf32.
// Block tile 128x128, BK=32. 8 warps (4 along M x 2 along N), warp tile 32x64.
// ---------------------------------------------------------------------------
__global__ __launch_bounds__(256) void gemm1_mma_tf32(
        const float* __restrict__ A, const float* __restrict__ W,
        __half* __restrict__ C, int M) {
    constexpr int BM = 128, BN = 128, BK = 32, LDA = 36;
    __shared__ float sA[BM * LDA];
    __shared__ float sB[BN * LDA];

    const int tid  = threadIdx.x;
    const int wid  = tid >> 5;
    const int lane = tid & 31;
    const int gid  = lane >> 2;
    const int tig  = lane & 3;
    const int warpM = (wid & 3) * 32;
    const int warpN = (wid >> 2) * 64;
    const int rowBase = blockIdx.x * BM;

    float acc[2][8][4];
    #pragma unroll
    for (int a = 0; a < 2; a++)
        #pragma unroll
        for (int b = 0; b < 8; b++)
            #pragma unroll
            for (int c = 0; c < 4; c++) acc[a][b][c] = 0.f;

    for (int k0 = 0; k0 < IN_DIM; k0 += BK) {
        #pragma unroll
        for (int i = 0; i < 4; i++) {
            int f = tid + i * 256;
            int r = f >> 3, q = f & 7;
            int m = rowBase + r;
            float4 v = make_float4(0.f, 0.f, 0.f, 0.f);
            if (m < M) v = *(const float4*)(A + (size_t)m * IN_DIM + k0 + q * 4);
            v.x = to_tf32_rn(v.x); v.y = to_tf32_rn(v.y);
            v.z = to_tf32_rn(v.z); v.w = to_tf32_rn(v.w);
            *(float4*)&sA[r * LDA + q * 4] = v;
        }
        #pragma unroll
        for (int i = 0; i < 16; i++) {
            int f = tid + i * 256;
            int kl = f >> 7, n = f & (BN - 1);
            sB[n * LDA + kl] = to_tf32_rn(W[(size_t)(k0 + kl) * BN + n]);
        }
        __syncthreads();

        #pragma unroll
        for (int kk = 0; kk < 4; kk++) {
            const int k = kk * 8;
            uint32_t bf[8][2];
            #pragma unroll
            for (int nt = 0; nt < 8; nt++) {
                int n = warpN + nt * 8 + gid;
                bf[nt][0] = __float_as_uint(sB[n * LDA + k + tig]);
                bf[nt][1] = __float_as_uint(sB[n * LDA + k + 4 + tig]);
            }
            #pragma unroll
            for (int mt = 0; mt < 2; mt++) {
                int r0 = warpM + mt * 16 + gid;
                uint32_t a0 = __float_as_uint(sA[r0 * LDA + k + tig]);
                uint32_t a1 = __float_as_uint(sA[(r0 + 8) * LDA + k + tig]);
                uint32_t a2 = __float_as_uint(sA[r0 * LDA + k + 4 + tig]);
                uint32_t a3 = __float_as_uint(sA[(r0 + 8) * LDA + k + 4 + tig]);
                #pragma unroll
                for (int nt = 0; nt < 8; nt++) {
                    asm volatile(
                        "mma.sync.aligned.m16n8k8.row.col.f32.tf32.tf32.f32 "
                        "{%0,%1,%2,%3}, {%4,%5,%6,%7}, {%8,%9}, {%0,%1,%2,%3};"
                        : "+f"(acc[mt][nt][0]), "+f"(acc[mt][nt][1]),
                          "+f"(acc[mt][nt][2]), "+f"(acc[mt][nt][3])
                        : "r"(a0), "r"(a1), "r"(a2), "r"(a3),
                          "r"(bf[nt][0]), "r"(bf[nt][1]));
                }
            }
        }
        __syncthreads();
    }

    #pragma unroll
    for (int mt = 0; mt < 2; mt++) {
        #pragma unroll
        for (int rr = 0; rr < 2; rr++) {
            int m = rowBase + warpM + mt * 16 + rr * 8 + gid;
            if (m < M) {
                __half* cp = C + (size_t)m * BN + warpN;
                #pragma unroll
                for (int nt = 0; nt < 8; nt++) {
                    *(__half2*)(cp + nt * 8 + 2 * tig) =
                        __floats2half2_rn(acc[mt][nt][rr * 2 + 0],
                                          acc[mt][nt][rr * 2 + 1]);
                }
            }
        }
    }
}

// ---------------------------------------------------------------------------
// fp32 SGEMM for layer 2 (ReLU fused on A load), fp16 output.
// ---------------------------------------------------------------------------
template<int BM, int BN, int BK, bool RELU>
__global__ void sgemm_kernel(const float* __restrict__ A,
                             const float* __restrict__ B,
                             __half* __restrict__ C, int M, int K) {
    constexpr int THREADS = (BM / 8) * (BN / 8);
    __shared__ float Ast[BK][BM];
    __shared__ float Bs[BK][BN];

    const int tid  = threadIdx.x;
    const int tcol = tid % (BN / 8);
    const int trow = tid / (BN / 8);
    const int rowBase = blockIdx.x * BM;

    float acc[8][8];
    #pragma unroll
    for (int i = 0; i < 8; i++)
        #pragma unroll
        for (int j = 0; j < 8; j++) acc[i][j] = 0.f;

    for (int k0 = 0; k0 < K; k0 += BK) {
        constexpr int A4 = BM * BK / 4;
        #pragma unroll
        for (int f = tid; f < A4; f += THREADS) {
            int r  = f / (BK / 4);
            int kq = f % (BK / 4);
            int grow = rowBase + r;
            float4 v = make_float4(0.f, 0.f, 0.f, 0.f);
            if (grow < M)
                v = *(const float4*)(A + (size_t)grow * K + k0 + kq * 4);
            if (RELU) {
                v.x = fmaxf(v.x, 0.f); v.y = fmaxf(v.y, 0.f);
                v.z = fmaxf(v.z, 0.f); v.w = fmaxf(v.w, 0.f);
            }
            Ast[kq * 4 + 0][r] = v.x;
            Ast[kq * 4 + 1][r] = v.y;
            Ast[kq * 4 + 2][r] = v.z;
            Ast[kq * 4 + 3][r] = v.w;
        }
        constexpr int B4 = BK * BN / 4;
        #pragma unroll
        for (int f = tid; f < B4; f += THREADS) {
            int kk = f / (BN / 4);
            int c4 = f % (BN / 4);
            *(float4*)&Bs[kk][c4 * 4] =
                *(const float4*)(B + (size_t)(k0 + kk) * BN + c4 * 4);
        }
        __syncthreads();

        #pragma unroll
        for (int kk = 0; kk < BK; kk++) {
            float4 a0 = *(const float4*)&Ast[kk][trow * 8];
            float4 a1 = *(const float4*)&Ast[kk][trow * 8 + 4];
            float4 b0 = *(const float4*)&Bs[kk][tcol * 8];
            float4 b1 = *(const float4*)&Bs[kk][tcol * 8 + 4];
            float a[8] = {a0.x, a0.y, a0.z, a0.w, a1.x, a1.y, a1.z, a1.w};
            float b[8] = {b0.x, b0.y, b0.z, b0.w, b1.x, b1.y, b1.z, b1.w};
            #pragma unroll
            for (int i = 0; i < 8; i++)
                #pragma unroll
                for (int j = 0; j < 8; j++)
                    acc[i][j] = fmaf(a[i], b[j], acc[i][j]);
        }
        __syncthreads();
    }

    #pragma unroll
    for (int i = 0; i < 8; i++) {
        int grow = rowBase + trow * 8 + i;
        if (grow < M) {
            __half* cp = C + (size_t)grow * BN + tcol * 8;
            __half2 h0 = __floats2half2_rn(acc[i][0], acc[i][1]);
            __half2 h1 = __floats2half2_rn(acc[i][2], acc[i][3]);
            __half2 h2 = __floats2half2_rn(acc[i][4], acc[i][5]);
            __half2 h3 = __floats2half2_rn(acc[i][6], acc[i][7]);
            uint4 u;
            u.x = *(uint32_t*)&h0; u.y = *(uint32_t*)&h1;
            u.z = *(uint32_t*)&h2; u.w = *(uint32_t*)&h3;
            *(uint4*)cp = u;
        }
    }
}

// ---------------------------------------------------------------------------
// CSR build
// ---------------------------------------------------------------------------
__global__ void zero_counts_kernel(int* __restrict__ cnt, int n) {
    int i = blockIdx.x * blockDim.x + threadIdx.x;
    if (i < n) cnt[i] = 0;
}

__global__ void hist_kernel(const int* __restrict__ rows, int* __restrict__ cnt, int E) {
    int e = blockIdx.x * blockDim.x + threadIdx.x;
    if (e < E) atomicAdd(&cnt[rows[e]], 1);
}

__global__ __launch_bounds__(1024) void scan_kernel(
        int* __restrict__ cnt_and_cursor, int* __restrict__ rowptr, int N, int E) {
    __shared__ int part[1024];
    const int t = threadIdx.x;
    const int chunk = (N + 1023) / 1024;
    const int lo = t * chunk;
    const int hi = min(lo + chunk, N);
    int s = 0;
    for (int i = lo; i < hi; i++) s += cnt_and_cursor[i];
    part[t] = s;
    __syncthreads();
    #pragma unroll
    for (int off = 1; off < 1024; off <<= 1) {
        int v = (t >= off) ? part[t - off] : 0;
        __syncthreads();
        part[t] += v;
        __syncthreads();
    }
    int base = (t == 0) ? 0 : part[t - 1];
    for (int i = lo; i < hi; i++) {
        int c = cnt_and_cursor[i];
        rowptr[i] = base;
        cnt_and_cursor[i] = base;
        base += c;
    }
    if (t == 0) rowptr[N] = E;
}

__global__ void scatter_kernel(const int* __restrict__ rows,
                               const int* __restrict__ cols,
                               const float* __restrict__ ew,
                               int* __restrict__ cursor,
                               int2* __restrict__ edges, int E) {
    int e = blockIdx.x * blockDim.x + threadIdx.x;
    if (e >= E) return;
    int r = rows[e];
    int pos = atomicAdd(&cursor[r], 1);
    edges[pos] = make_int2(cols[e], __float_as_int(ew[e]));
}

// ---------------------------------------------------------------------------
// CSR SpMM, fp16 payload, row range [row0, rowEnd).
// ---------------------------------------------------------------------------
template<int VEC>
__global__ void csr_spmm_h_kernel(const int* __restrict__ rowptr,
                                  const int2* __restrict__ edges,
                                  const __half* __restrict__ src,
                                  const float* __restrict__ bias,
                                  float* __restrict__ dst,
                                  int row0, int rowEnd) {
    constexpr int D = VEC * 32;
    const int lane = threadIdx.x & 31;
    const int row  = row0 + blockIdx.x * (blockDim.x >> 5) + (threadIdx.x >> 5);
    if (row >= rowEnd) return;

    const int s = rowptr[row];
    const int e = rowptr[row + 1];

    float acc[VEC];
    #pragma unroll
    for (int v = 0; v < VEC; v++) acc[v] = bias[lane * VEC + v];

    int j = s;
    for (; j + 2 <= e; j += 2) {
        int2 e0 = edges[j], e1 = edges[j + 1];
        float w0 = __int_as_float(e0.y), w1 = __int_as_float(e1.y);
        const __half* p0 = src + (size_t)e0.x * D + lane * VEC;
        const __half* p1 = src + (size_t)e1.x * D + lane * VEC;
        if (VEC == 4) {
            uint2 u0 = *(const uint2*)p0;
            uint2 u1 = *(const uint2*)p1;
            float2 a0 = __half22float2(*(const __half2*)&u0.x);
            float2 a1 = __half22float2(*(const __half2*)&u0.y);
            float2 c0 = __half22float2(*(const __half2*)&u1.x);
            float2 c1 = __half22float2(*(const __half2*)&u1.y);
            acc[0] = fmaf(w0, a0.x, fmaf(w1, c0.x, acc[0]));
            acc[1] = fmaf(w0, a0.y, fmaf(w1, c0.y, acc[1]));
            acc[2] = fmaf(w0, a1.x, fmaf(w1, c1.x, acc[2]));
            acc[3] = fmaf(w0, a1.y, fmaf(w1, c1.y, acc[3]));
        } else {
            float2 a0 = __half22float2(*(const __half2*)p0);
            float2 c0 = __half22float2(*(const __half2*)p1);
            acc[0] = fmaf(w0, a0.x, fmaf(w1, c0.x, acc[0]));
            acc[1] = fmaf(w0, a0.y, fmaf(w1, c0.y, acc[1]));
        }
    }
    if (j < e) {
        int2 e0 = edges[j];
        float w0 = __int_as_float(e0.y);
        const __half* p0 = src + (size_t)e0.x * D + lane * VEC;
        if (VEC == 4) {
            uint2 u0 = *(const uint2*)p0;
            float2 a0 = __half22float2(*(const __half2*)&u0.x);
            float2 a1 = __half22float2(*(const __half2*)&u0.y);
            acc[0] = fmaf(w0, a0.x, acc[0]);
            acc[1] = fmaf(w0, a0.y, acc[1]);
            acc[2] = fmaf(w0, a1.x, acc[2]);
            acc[3] = fmaf(w0, a1.y, acc[3]);
        } else {
            float2 a0 = __half22float2(*(const __half2*)p0);
            acc[0] = fmaf(w0, a0.x, acc[0]);
            acc[1] = fmaf(w0, a0.y, acc[1]);
        }
    }

    float* dp = dst + (size_t)row * D + lane * VEC;
    if (VEC == 4)
        *(float4*)dp = make_float4(acc[0], acc[1], acc[2], acc[3]);
    else
        *(float2*)dp = make_float2(acc[0], acc[1]);
}

// ---------------------------------------------------------------------------
extern "C" void kernel_launch(void* const* d_in, const int* in_sizes, int n_in,
                              void* d_out, int out_size) {
    const float* x  = (const float*)d_in[0];
    const int*   ei = (const int*)d_in[1];     // [2, E] int32
    const float* ew = (const float*)d_in[2];
    const float* W1 = (const float*)d_in[3];
    const float* b1 = (const float*)d_in[4];
    const float* W2 = (const float*)d_in[5];
    const float* b2 = (const float*)d_in[6];
    float* out = (float*)d_out;

    const int M = in_sizes[0] / IN_DIM;   // 50000
    const int E = in_sizes[2];            // 1600000

    __half *S1, *S2;
    float *H;
    int *rowptr, *rowaux;
    int2 *edges;
    cudaGetSymbolAddress((void**)&S1, g_S1);
    cudaGetSymbolAddress((void**)&H,  g_H);
    cudaGetSymbolAddress((void**)&S2, g_S2);
    cudaGetSymbolAddress((void**)&rowptr, g_rowptr);
    cudaGetSymbolAddress((void**)&rowaux, g_rowaux);
    cudaGetSymbolAddress((void**)&edges,  g_edges);

    const int* e_rows = ei;
    const int* e_cols = ei + E;

    static cudaStream_t s_side = nullptr;
    static cudaEvent_t  ev_fork = nullptr, ev_join = nullptr,
                        ev_h0 = nullptr, ev_g2 = nullptr;
    if (s_side == nullptr) {
        cudaStreamCreateWithFlags(&s_side, cudaStreamNonBlocking);
        cudaEventCreateWithFlags(&ev_fork, cudaEventDisableTiming);
        cudaEventCreateWithFlags(&ev_join, cudaEventDisableTiming);
        cudaEventCreateWithFlags(&ev_h0,   cudaEventDisableTiming);
        cudaEventCreateWithFlags(&ev_g2,   cudaEventDisableTiming);
    }

    // Row split for the spmm1/GEMM2 pipeline (multiple of 128)
    const int Mh = ((M / 2) / 128) * 128;       // 24960

    // ---- fork: CSR build on side stream, GEMM1 on main ----
    cudaEventRecord(ev_fork, 0);
    cudaStreamWaitEvent(s_side, ev_fork, 0);

    zero_counts_kernel<<<(M + 255) / 256, 256, 0, s_side>>>(rowaux, M);
    hist_kernel<<<(E + 255) / 256, 256, 0, s_side>>>(e_rows, rowaux, E);
    scan_kernel<<<1, 1024, 0, s_side>>>(rowaux, rowptr, M, E);
    scatter_kernel<<<(E + 255) / 256, 256, 0, s_side>>>(e_rows, e_cols, ew,
                                                        rowaux, edges, E);
    cudaEventRecord(ev_join, s_side);

    // GEMM1: S1 = x @ W1 (tf32 mma, fp16 out) — concurrent with CSR build
    gemm1_mma_tf32<<<(M + 127) / 128, 256>>>(x, W1, S1, M);

    // ---- join build ----
    cudaStreamWaitEvent(0, ev_join, 0);

    // SpMM1 half0: rows [0, Mh)
    csr_spmm_h_kernel<4><<<(Mh + 7) / 8, 256>>>(rowptr, edges, S1, b1, H, 0, Mh);
    cudaEventRecord(ev_h0, 0);

    // GEMM2 half0 on side stream (needs only H[0..Mh))
    cudaStreamWaitEvent(s_side, ev_h0, 0);
    sgemm_kernel<128, OUT_DIM, 16, true>
        <<<(Mh + 127) / 128, (128 / 8) * (OUT_DIM / 8), 0, s_side>>>(
            H, W2, S2, Mh, HID_DIM);
    cudaEventRecord(ev_g2, s_side);

    // SpMM1 half1 on main (concurrent with GEMM2 half0)
    csr_spmm_h_kernel<4><<<(M - Mh + 7) / 8, 256>>>(rowptr, edges, S1, b1, H, Mh, M);

    // GEMM2 half1 on main
    sgemm_kernel<128, OUT_DIM, 16, true>
        <<<(M - Mh + 127) / 128, (128 / 8) * (OUT_DIM / 8)>>>(
            H + (size_t)Mh * HID_DIM, W2, S2 + (size_t)Mh * OUT_DIM,
            M - Mh, HID_DIM);

    // join GEMM2 half0, then SpMM2 (needs all of S2)
    cudaStreamWaitEvent(0, ev_g2, 0);
    csr_spmm_h_kernel<2><<<(M + 7) / 8, 256>>>(rowptr, edges, S2, b2, out, 0, M);
}

// round 13
// speedup vs baseline: 1.1028x; 1.1028x over previous
#include <cuda_runtime.h>
#include <cuda_fp16.h>
#include <cstdint>

// GCN: out = spmm(A, relu(spmm(A, x@W1)+b1) @ W2) + b2
// N=50000, E=1.6M, 512 -> 128 -> 64.
// GEMM1: fp16 mma.m16n8k16 + ldmatrix -> S1 fp16. GEMM2: fp32 FFMA -> S2 fp16.
// SpMM: on-device CSR (int2 {col,w}) + warp-per-row, fp16 gather payload.
// Overlap: CSR build || GEMM1 (graph fork/join). Sequence otherwise serial (R11).
// edge_index is int32 on device (JAX default config downcasts int64).

#define IN_DIM  512
#define HID_DIM 128
#define OUT_DIM 64
#define N_MAX   50000
#define E_MAX   1600000

__device__ __half g_S1[(size_t)N_MAX * HID_DIM];  // x @ W1        (fp16)
__device__ float  g_H [(size_t)N_MAX * HID_DIM];  // spmm1 out +b1 (fp32)
__device__ __half g_S2[(size_t)N_MAX * OUT_DIM];  // relu(H) @ W2  (fp16)

// CSR scratch
__device__ int  g_rowptr[N_MAX + 1];
__device__ int  g_rowaux[N_MAX];
__device__ int2 g_edges [E_MAX];      // {colidx, weight-as-int}

// ---------------------------------------------------------------------------
// GEMM1: S1[M,128] = x[M,512] @ W1[512,128], fp16 mma.m16n8k16, fp32 accum.
// Block tile 128x128, BK=32. 8 warps (4 M x 2 N), warp tile 32x64.
// Smem fp16, row stride 40 halfs (80B): granule walk 5*row mod 8 -> ldmatrix
// conflict-free.
// ---------------------------------------------------------------------------
__global__ __launch_bounds__(256) void gemm1_mma_f16(
        const float* __restrict__ A, const float* __restrict__ W,
        __half* __restrict__ C, int M) {
    constexpr int BM = 128, BN = 128, BK = 32, LDH = 40;
    __shared__ __half sA[BM * LDH];   // [m][k]
    __shared__ __half sB[BN * LDH];   // [n][k] (transposed W)

    const int tid  = threadIdx.x;
    const int wid  = tid >> 5;
    const int lane = tid & 31;
    const int gid  = lane >> 2;
    const int tig  = lane & 3;
    const int warpM = (wid & 3) * 32;
    const int warpN = (wid >> 2) * 64;
    const int rowBase = blockIdx.x * BM;

    // ldmatrix per-lane source coordinates
    const int a_row = ((lane >> 3) & 1) * 8 + (lane & 7);  // + warpM + mt*16
    const int a_koff = (lane >> 4) * 8;
    const int b_n   = (lane >> 4) * 8 + (lane & 7);        // + warpN + ntp*16
    const int b_koff = ((lane >> 3) & 1) * 8;

    const uint32_t sA_u = (uint32_t)__cvta_generic_to_shared(sA);
    const uint32_t sB_u = (uint32_t)__cvta_generic_to_shared(sB);

    float acc[2][8][4];
    #pragma unroll
    for (int a = 0; a < 2; a++)
        #pragma unroll
        for (int b = 0; b < 8; b++)
            #pragma unroll
            for (int c = 0; c < 4; c++) acc[a][b][c] = 0.f;

    for (int k0 = 0; k0 < IN_DIM; k0 += BK) {
        // ---- A tile: 128 x 32, fp32 -> fp16 (4 floats -> 8B store) ----
        #pragma unroll
        for (int i = 0; i < 4; i++) {
            int f = tid + i * 256;
            int r = f >> 3, q = f & 7;
            int m = rowBase + r;
            float4 v = make_float4(0.f, 0.f, 0.f, 0.f);
            if (m < M) v = *(const float4*)(A + (size_t)m * IN_DIM + k0 + q * 4);
            __half2 h0 = __floats2half2_rn(v.x, v.y);
            __half2 h1 = __floats2half2_rn(v.z, v.w);
            uint2 u;
            u.x = *(uint32_t*)&h0; u.y = *(uint32_t*)&h1;
            *(uint2*)&sA[r * LDH + q * 4] = u;
        }
        // ---- B tile: sB[n][k] = W[k0+k][n], half2 over k pair ----
        #pragma unroll
        for (int i = 0; i < 8; i++) {
            int f = tid + i * 256;
            int n = f & (BN - 1), kp = f >> 7;     // kp: 0..15
            float w0 = W[(size_t)(k0 + 2 * kp) * BN + n];
            float w1 = W[(size_t)(k0 + 2 * kp + 1) * BN + n];
            __half2 h = __floats2half2_rn(w0, w1);
            *(__half2*)&sB[n * LDH + 2 * kp] = h;
        }
        __syncthreads();

        #pragma unroll
        for (int ks = 0; ks < 2; ks++) {      // two k16 steps per BK=32
            uint32_t af[2][4];
            #pragma unroll
            for (int mt = 0; mt < 2; mt++) {
                uint32_t addr = sA_u +
                    ((warpM + mt * 16 + a_row) * LDH + ks * 16 + a_koff) * 2;
                asm volatile(
                    "ldmatrix.sync.aligned.m8n8.x4.shared.b16 {%0,%1,%2,%3}, [%4];"
                    : "=r"(af[mt][0]), "=r"(af[mt][1]),
                      "=r"(af[mt][2]), "=r"(af[mt][3])
                    : "r"(addr));
            }
            uint32_t bf[4][4];
            #pragma unroll
            for (int ntp = 0; ntp < 4; ntp++) {
                uint32_t addr = sB_u +
                    ((warpN + ntp * 16 + b_n) * LDH + ks * 16 + b_koff) * 2;
                asm volatile(
                    "ldmatrix.sync.aligned.m8n8.x4.shared.b16 {%0,%1,%2,%3}, [%4];"
                    : "=r"(bf[ntp][0]), "=r"(bf[ntp][1]),
                      "=r"(bf[ntp][2]), "=r"(bf[ntp][3])
                    : "r"(addr));
            }
            #pragma unroll
            for (int mt = 0; mt < 2; mt++) {
                #pragma unroll
                for (int ntp = 0; ntp < 4; ntp++) {
                    #pragma unroll
                    for (int hh = 0; hh < 2; hh++) {
                        int nt = ntp * 2 + hh;
                        asm volatile(
                            "mma.sync.aligned.m16n8k16.row.col.f32.f16.f16.f32 "
                            "{%0,%1,%2,%3}, {%4,%5,%6,%7}, {%8,%9}, {%0,%1,%2,%3};"
                            : "+f"(acc[mt][nt][0]), "+f"(acc[mt][nt][1]),
                              "+f"(acc[mt][nt][2]), "+f"(acc[mt][nt][3])
                            : "r"(af[mt][0]), "r"(af[mt][1]),
                              "r"(af[mt][2]), "r"(af[mt][3]),
                              "r"(bf[ntp][hh * 2 + 0]), "r"(bf[ntp][hh * 2 + 1]));
                    }
                }
            }
        }
        __syncthreads();
    }

    #pragma unroll
    for (int mt = 0; mt < 2; mt++) {
        #pragma unroll
        for (int rr = 0; rr < 2; rr++) {
            int m = rowBase + warpM + mt * 16 + rr * 8 + gid;
            if (m < M) {
                __half* cp = C + (size_t)m * BN + warpN;
                #pragma unroll
                for (int nt = 0; nt < 8; nt++) {
                    *(__half2*)(cp + nt * 8 + 2 * tig) =
                        __floats2half2_rn(acc[mt][nt][rr * 2 + 0],
                                          acc[mt][nt][rr * 2 + 1]);
                }
            }
        }
    }
}

// ---------------------------------------------------------------------------
// fp32 SGEMM for layer 2 (ReLU fused on A load), fp16 output.
// ---------------------------------------------------------------------------
template<int BM, int BN, int BK, bool RELU>
__global__ void sgemm_kernel(const float* __restrict__ A,
                             const float* __restrict__ B,
                             __half* __restrict__ C, int M, int K) {
    constexpr int THREADS = (BM / 8) * (BN / 8);
    __shared__ float Ast[BK][BM];
    __shared__ float Bs[BK][BN];

    const int tid  = threadIdx.x;
    const int tcol = tid % (BN / 8);
    const int trow = tid / (BN / 8);
    const int rowBase = blockIdx.x * BM;

    float acc[8][8];
    #pragma unroll
    for (int i = 0; i < 8; i++)
        #pragma unroll
        for (int j = 0; j < 8; j++) acc[i][j] = 0.f;

    for (int k0 = 0; k0 < K; k0 += BK) {
        constexpr int A4 = BM * BK / 4;
        #pragma unroll
        for (int f = tid; f < A4; f += THREADS) {
            int r  = f / (BK / 4);
            int kq = f % (BK / 4);
            int grow = rowBase + r;
            float4 v = make_float4(0.f, 0.f, 0.f, 0.f);
            if (grow < M)
                v = *(const float4*)(A + (size_t)grow * K + k0 + kq * 4);
            if (RELU) {
                v.x = fmaxf(v.x, 0.f); v.y = fmaxf(v.y, 0.f);
                v.z = fmaxf(v.z, 0.f); v.w = fmaxf(v.w, 0.f);
            }
            Ast[kq * 4 + 0][r] = v.x;
            Ast[kq * 4 + 1][r] = v.y;
            Ast[kq * 4 + 2][r] = v.z;
            Ast[kq * 4 + 3][r] = v.w;
        }
        constexpr int B4 = BK * BN / 4;
        #pragma unroll
        for (int f = tid; f < B4; f += THREADS) {
            int kk = f / (BN / 4);
            int c4 = f % (BN / 4);
            *(float4*)&Bs[kk][c4 * 4] =
                *(const float4*)(B + (size_t)(k0 + kk) * BN + c4 * 4);
        }
        __syncthreads();

        #pragma unroll
        for (int kk = 0; kk < BK; kk++) {
            float4 a0 = *(const float4*)&Ast[kk][trow * 8];
            float4 a1 = *(const float4*)&Ast[kk][trow * 8 + 4];
            float4 b0 = *(const float4*)&Bs[kk][tcol * 8];
            float4 b1 = *(const float4*)&Bs[kk][tcol * 8 + 4];
            float a[8] = {a0.x, a0.y, a0.z, a0.w, a1.x, a1.y, a1.z, a1.w};
            float b[8] = {b0.x, b0.y, b0.z, b0.w, b1.x, b1.y, b1.z, b1.w};
            #pragma unroll
            for (int i = 0; i < 8; i++)
                #pragma unroll
                for (int j = 0; j < 8; j++)
                    acc[i][j] = fmaf(a[i], b[j], acc[i][j]);
        }
        __syncthreads();
    }

    #pragma unroll
    for (int i = 0; i < 8; i++) {
        int grow = rowBase + trow * 8 + i;
        if (grow < M) {
            __half* cp = C + (size_t)grow * BN + tcol * 8;
            __half2 h0 = __floats2half2_rn(acc[i][0], acc[i][1]);
            __half2 h1 = __floats2half2_rn(acc[i][2], acc[i][3]);
            __half2 h2 = __floats2half2_rn(acc[i][4], acc[i][5]);
            __half2 h3 = __floats2half2_rn(acc[i][6], acc[i][7]);
            uint4 u;
            u.x = *(uint32_t*)&h0; u.y = *(uint32_t*)&h1;
            u.z = *(uint32_t*)&h2; u.w = *(uint32_t*)&h3;
            *(uint4*)cp = u;
        }
    }
}

// ---------------------------------------------------------------------------
// CSR build
// ---------------------------------------------------------------------------
__global__ void zero_counts_kernel(int* __restrict__ cnt, int n) {
    int i = blockIdx.x * blockDim.x + threadIdx.x;
    if (i < n) cnt[i] = 0;
}

__global__ void hist_kernel(const int* __restrict__ rows, int* __restrict__ cnt, int E) {
    int e = blockIdx.x * blockDim.x + threadIdx.x;
    if (e < E) atomicAdd(&cnt[rows[e]], 1);
}

__global__ __launch_bounds__(1024) void scan_kernel(
        int* __restrict__ cnt_and_cursor, int* __restrict__ rowptr, int N, int E) {
    __shared__ int part[1024];
    const int t = threadIdx.x;
    const int chunk = (N + 1023) / 1024;
    const int lo = t * chunk;
    const int hi = min(lo + chunk, N);
    int s = 0;
    for (int i = lo; i < hi; i++) s += cnt_and_cursor[i];
    part[t] = s;
    __syncthreads();
    #pragma unroll
    for (int off = 1; off < 1024; off <<= 1) {
        int v = (t >= off) ? part[t - off] : 0;
        __syncthreads();
        part[t] += v;
        __syncthreads();
    }
    int base = (t == 0) ? 0 : part[t - 1];
    for (int i = lo; i < hi; i++) {
        int c = cnt_and_cursor[i];
        rowptr[i] = base;
        cnt_and_cursor[i] = base;
        base += c;
    }
    if (t == 0) rowptr[N] = E;
}

__global__ void scatter_kernel(const int* __restrict__ rows,
                               const int* __restrict__ cols,
                               const float* __restrict__ ew,
                               int* __restrict__ cursor,
                               int2* __restrict__ edges, int E) {
    int e = blockIdx.x * blockDim.x + threadIdx.x;
    if (e >= E) return;
    int r = rows[e];
    int pos = atomicAdd(&cursor[r], 1);
    edges[pos] = make_int2(cols[e], __float_as_int(ew[e]));
}

// ---------------------------------------------------------------------------
// CSR SpMM, fp16 payload: warp per row, VEC fp16 per lane (D = 32*VEC).
// ---------------------------------------------------------------------------
template<int VEC>
__global__ void csr_spmm_h_kernel(const int* __restrict__ rowptr,
                                  const int2* __restrict__ edges,
                                  const __half* __restrict__ src,
                                  const float* __restrict__ bias,
                                  float* __restrict__ dst, int N) {
    constexpr int D = VEC * 32;
    const int lane = threadIdx.x & 31;
    const int row  = blockIdx.x * (blockDim.x >> 5) + (threadIdx.x >> 5);
    if (row >= N) return;

    const int s = rowptr[row];
    const int e = rowptr[row + 1];

    float acc[VEC];
    #pragma unroll
    for (int v = 0; v < VEC; v++) acc[v] = bias[lane * VEC + v];

    int j = s;
    for (; j + 2 <= e; j += 2) {
        int2 e0 = edges[j], e1 = edges[j + 1];
        float w0 = __int_as_float(e0.y), w1 = __int_as_float(e1.y);
        const __half* p0 = src + (size_t)e0.x * D + lane * VEC;
        const __half* p1 = src + (size_t)e1.x * D + lane * VEC;
        if (VEC == 4) {
            uint2 u0 = *(const uint2*)p0;
            uint2 u1 = *(const uint2*)p1;
            float2 a0 = __half22float2(*(const __half2*)&u0.x);
            float2 a1 = __half22float2(*(const __half2*)&u0.y);
            float2 c0 = __half22float2(*(const __half2*)&u1.x);
            float2 c1 = __half22float2(*(const __half2*)&u1.y);
            acc[0] = fmaf(w0, a0.x, fmaf(w1, c0.x, acc[0]));
            acc[1] = fmaf(w0, a0.y, fmaf(w1, c0.y, acc[1]));
            acc[2] = fmaf(w0, a1.x, fmaf(w1, c1.x, acc[2]));
            acc[3] = fmaf(w0, a1.y, fmaf(w1, c1.y, acc[3]));
        } else {
            float2 a0 = __half22float2(*(const __half2*)p0);
            float2 c0 = __half22float2(*(const __half2*)p1);
            acc[0] = fmaf(w0, a0.x, fmaf(w1, c0.x, acc[0]));
            acc[1] = fmaf(w0, a0.y, fmaf(w1, c0.y, acc[1]));
        }
    }
    if (j < e) {
        int2 e0 = edges[j];
        float w0 = __int_as_float(e0.y);
        const __half* p0 = src + (size_t)e0.x * D + lane * VEC;
        if (VEC == 4) {
            uint2 u0 = *(const uint2*)p0;
            float2 a0 = __half22float2(*(const __half2*)&u0.x);
            float2 a1 = __half22float2(*(const __half2*)&u0.y);
            acc[0] = fmaf(w0, a0.x, acc[0]);
            acc[1] = fmaf(w0, a0.y, acc[1]);
            acc[2] = fmaf(w0, a1.x, acc[2]);
            acc[3] = fmaf(w0, a1.y, acc[3]);
        } else {
            float2 a0 = __half22float2(*(const __half2*)p0);
            acc[0] = fmaf(w0, a0.x, acc[0]);
            acc[1] = fmaf(w0, a0.y, acc[1]);
        }
    }

    float* dp = dst + (size_t)row * D + lane * VEC;
    if (VEC == 4)
        *(float4*)dp = make_float4(acc[0], acc[1], acc[2], acc[3]);
    else
        *(float2*)dp = make_float2(acc[0], acc[1]);
}

// ---------------------------------------------------------------------------
extern "C" void kernel_launch(void* const* d_in, const int* in_sizes, int n_in,
                              void* d_out, int out_size) {
    const float* x  = (const float*)d_in[0];
    const int*   ei = (const int*)d_in[1];     // [2, E] int32
    const float* ew = (const float*)d_in[2];
    const float* W1 = (const float*)d_in[3];
    const float* b1 = (const float*)d_in[4];
    const float* W2 = (const float*)d_in[5];
    const float* b2 = (const float*)d_in[6];
    float* out = (float*)d_out;

    const int M = in_sizes[0] / IN_DIM;   // 50000
    const int E = in_sizes[2];            // 1600000

    __half *S1, *S2;
    float *H;
    int *rowptr, *rowaux;
    int2 *edges;
    cudaGetSymbolAddress((void**)&S1, g_S1);
    cudaGetSymbolAddress((void**)&H,  g_H);
    cudaGetSymbolAddress((void**)&S2, g_S2);
    cudaGetSymbolAddress((void**)&rowptr, g_rowptr);
    cudaGetSymbolAddress((void**)&rowaux, g_rowaux);
    cudaGetSymbolAddress((void**)&edges,  g_edges);

    const int* e_rows = ei;
    const int* e_cols = ei + E;

    static cudaStream_t s_build = nullptr;
    static cudaEvent_t  ev_fork = nullptr, ev_join = nullptr;
    if (s_build == nullptr) {
        cudaStreamCreateWithFlags(&s_build, cudaStreamNonBlocking);
        cudaEventCreateWithFlags(&ev_fork, cudaEventDisableTiming);
        cudaEventCreateWithFlags(&ev_join, cudaEventDisableTiming);
    }

    // ---- fork: CSR build on side stream, GEMM1 on main ----
    cudaEventRecord(ev_fork, 0);
    cudaStreamWaitEvent(s_build, ev_fork, 0);

    zero_counts_kernel<<<(M + 255) / 256, 256, 0, s_build>>>(rowaux, M);
    hist_kernel<<<(E + 255) / 256, 256, 0, s_build>>>(e_rows, rowaux, E);
    scan_kernel<<<1, 1024, 0, s_build>>>(rowaux, rowptr, M, E);
    scatter_kernel<<<(E + 255) / 256, 256, 0, s_build>>>(e_rows, e_cols, ew,
                                                         rowaux, edges, E);
    cudaEventRecord(ev_join, s_build);

    // GEMM1: S1 = x @ W1 (fp16 mma, fp16 out) — concurrent with CSR build
    gemm1_mma_f16<<<(M + 127) / 128, 256>>>(x, W1, S1, M);

    // ---- join ----
    cudaStreamWaitEvent(0, ev_join, 0);

    // SpMM1: H = A @ S1 + b1   (fp16 gather, fp32 accumulate)
    csr_spmm_h_kernel<4><<<(M + 7) / 8, 256>>>(rowptr, edges, S1, b1, H, M);

    // GEMM2: S2 = relu(H) @ W2 (fp32 FFMA, fp16 out)
    sgemm_kernel<128, OUT_DIM, 16, true>
        <<<(M + 127) / 128, (128 / 8) * (OUT_DIM / 8)>>>(H, W2, S2, M, HID_DIM);

    // SpMM2: out = A @ S2 + b2  (fp16 gather, fp32 accumulate/output)
    csr_spmm_h_kernel<2><<<(M + 7) / 8, 256>>>(rowptr, edges, S2, b2, out, M);
}

// round 14
// speedup vs baseline: 1.1717x; 1.0625x over previous
#include <cuda_runtime.h>
#include <cuda_fp16.h>
#include <cstdint>

// GCN: out = spmm(A, relu(spmm(A, x@W1)+b1) @ W2) + b2
// N=50000, E=1.6M, 512 -> 128 -> 64.
// GEMM1: fp16 mma.m16n8k16 + ldmatrix (fp32 in) -> S1 fp16.
// SpMM1: CSR warp-per-row, fp16 gather, fused bias+ReLU -> H fp16.
// GEMM2: fp16 mma.m16n8k16 + ldmatrix (fp16 in)  -> S2 fp16.
// SpMM2: CSR warp-per-row, fp16 gather -> fp32 out.
// Overlap: CSR build || GEMM1 (graph fork/join).
// edge_index is int32 on device (JAX default config downcasts int64).

#define IN_DIM  512
#define HID_DIM 128
#define OUT_DIM 64
#define N_MAX   50000
#define E_MAX   1600000

__device__ __half g_S1[(size_t)N_MAX * HID_DIM];  // x @ W1              (fp16)
__device__ __half g_H [(size_t)N_MAX * HID_DIM];  // relu(spmm1 + b1)   (fp16)
__device__ __half g_S2[(size_t)N_MAX * OUT_DIM];  // H @ W2             (fp16)

// CSR scratch
__device__ int  g_rowptr[N_MAX + 1];
__device__ int  g_rowaux[N_MAX];
__device__ int2 g_edges [E_MAX];      // {colidx, weight-as-int}

// ---------------------------------------------------------------------------
// GEMM1: S1[M,128] = x[M,512] @ W1[512,128], fp16 mma.m16n8k16, fp32 accum.
// Block tile 128x128, BK=32, 8 warps (4 M x 2 N). LDH=40 halfs -> conflict-free
// ldmatrix (granule walk 5*row mod 8).
// ---------------------------------------------------------------------------
__global__ __launch_bounds__(256) void gemm1_mma_f16(
        const float* __restrict__ A, const float* __restrict__ W,
        __half* __restrict__ C, int M) {
    constexpr int BM = 128, BN = 128, BK = 32, LDH = 40;
    __shared__ __half sA[BM * LDH];
    __shared__ __half sB[BN * LDH];

    const int tid  = threadIdx.x;
    const int wid  = tid >> 5;
    const int lane = tid & 31;
    const int gid  = lane >> 2;
    const int tig  = lane & 3;
    const int warpM = (wid & 3) * 32;
    const int warpN = (wid >> 2) * 64;
    const int rowBase = blockIdx.x * BM;

    const int a_row = ((lane >> 3) & 1) * 8 + (lane & 7);
    const int a_koff = (lane >> 4) * 8;
    const int b_n   = (lane >> 4) * 8 + (lane & 7);
    const int b_koff = ((lane >> 3) & 1) * 8;

    const uint32_t sA_u = (uint32_t)__cvta_generic_to_shared(sA);
    const uint32_t sB_u = (uint32_t)__cvta_generic_to_shared(sB);

    float acc[2][8][4];
    #pragma unroll
    for (int a = 0; a < 2; a++)
        #pragma unroll
        for (int b = 0; b < 8; b++)
            #pragma unroll
            for (int c = 0; c < 4; c++) acc[a][b][c] = 0.f;

    for (int k0 = 0; k0 < IN_DIM; k0 += BK) {
        #pragma unroll
        for (int i = 0; i < 4; i++) {
            int f = tid + i * 256;
            int r = f >> 3, q = f & 7;
            int m = rowBase + r;
            float4 v = make_float4(0.f, 0.f, 0.f, 0.f);
            if (m < M) v = *(const float4*)(A + (size_t)m * IN_DIM + k0 + q * 4);
            __half2 h0 = __floats2half2_rn(v.x, v.y);
            __half2 h1 = __floats2half2_rn(v.z, v.w);
            uint2 u;
            u.x = *(uint32_t*)&h0; u.y = *(uint32_t*)&h1;
            *(uint2*)&sA[r * LDH + q * 4] = u;
        }
        #pragma unroll
        for (int i = 0; i < 8; i++) {
            int f = tid + i * 256;
            int n = f & (BN - 1), kp = f >> 7;
            float w0 = W[(size_t)(k0 + 2 * kp) * BN + n];
            float w1 = W[(size_t)(k0 + 2 * kp + 1) * BN + n];
            *(__half2*)&sB[n * LDH + 2 * kp] = __floats2half2_rn(w0, w1);
        }
        __syncthreads();

        #pragma unroll
        for (int ks = 0; ks < 2; ks++) {
            uint32_t af[2][4];
            #pragma unroll
            for (int mt = 0; mt < 2; mt++) {
                uint32_t addr = sA_u +
                    ((warpM + mt * 16 + a_row) * LDH + ks * 16 + a_koff) * 2;
                asm volatile(
                    "ldmatrix.sync.aligned.m8n8.x4.shared.b16 {%0,%1,%2,%3}, [%4];"
                    : "=r"(af[mt][0]), "=r"(af[mt][1]),
                      "=r"(af[mt][2]), "=r"(af[mt][3])
                    : "r"(addr));
            }
            uint32_t bf[4][4];
            #pragma unroll
            for (int ntp = 0; ntp < 4; ntp++) {
                uint32_t addr = sB_u +
                    ((warpN + ntp * 16 + b_n) * LDH + ks * 16 + b_koff) * 2;
                asm volatile(
                    "ldmatrix.sync.aligned.m8n8.x4.shared.b16 {%0,%1,%2,%3}, [%4];"
                    : "=r"(bf[ntp][0]), "=r"(bf[ntp][1]),
                      "=r"(bf[ntp][2]), "=r"(bf[ntp][3])
                    : "r"(addr));
            }
            #pragma unroll
            for (int mt = 0; mt < 2; mt++)
                #pragma unroll
                for (int ntp = 0; ntp < 4; ntp++)
                    #pragma unroll
                    for (int hh = 0; hh < 2; hh++) {
                        int nt = ntp * 2 + hh;
                        asm volatile(
                            "mma.sync.aligned.m16n8k16.row.col.f32.f16.f16.f32 "
                            "{%0,%1,%2,%3}, {%4,%5,%6,%7}, {%8,%9}, {%0,%1,%2,%3};"
                            : "+f"(acc[mt][nt][0]), "+f"(acc[mt][nt][1]),
                              "+f"(acc[mt][nt][2]), "+f"(acc[mt][nt][3])
                            : "r"(af[mt][0]), "r"(af[mt][1]),
                              "r"(af[mt][2]), "r"(af[mt][3]),
                              "r"(bf[ntp][hh * 2 + 0]), "r"(bf[ntp][hh * 2 + 1]));
                    }
        }
        __syncthreads();
    }

    #pragma unroll
    for (int mt = 0; mt < 2; mt++)
        #pragma unroll
        for (int rr = 0; rr < 2; rr++) {
            int m = rowBase + warpM + mt * 16 + rr * 8 + gid;
            if (m < M) {
                __half* cp = C + (size_t)m * BN + warpN;
                #pragma unroll
                for (int nt = 0; nt < 8; nt++)
                    *(__half2*)(cp + nt * 8 + 2 * tig) =
                        __floats2half2_rn(acc[mt][nt][rr * 2 + 0],
                                          acc[mt][nt][rr * 2 + 1]);
            }
        }
}

// ---------------------------------------------------------------------------
// GEMM2: S2[M,64] = H[M,128] @ W2[128,64], fp16 in (H), fp16 mma, fp32 accum.
// Block tile 128x64, BK=32, 8 warps (4 M x 2 N), warp tile 32x32.
// ---------------------------------------------------------------------------
__global__ __launch_bounds__(256) void gemm2_mma_f16(
        const __half* __restrict__ A, const float* __restrict__ W,
        __half* __restrict__ C, int M) {
    constexpr int BM = 128, BN = 64, BK = 32, K = HID_DIM, LDH = 40;
    __shared__ __half sA[BM * LDH];
    __shared__ __half sB[BN * LDH];

    const int tid  = threadIdx.x;
    const int wid  = tid >> 5;
    const int lane = tid & 31;
    const int gid  = lane >> 2;
    const int tig  = lane & 3;
    const int warpM = (wid & 3) * 32;
    const int warpN = (wid >> 2) * 32;
    const int rowBase = blockIdx.x * BM;

    const int a_row = ((lane >> 3) & 1) * 8 + (lane & 7);
    const int a_koff = (lane >> 4) * 8;
    const int b_n   = (lane >> 4) * 8 + (lane & 7);
    const int b_koff = ((lane >> 3) & 1) * 8;

    const uint32_t sA_u = (uint32_t)__cvta_generic_to_shared(sA);
    const uint32_t sB_u = (uint32_t)__cvta_generic_to_shared(sB);

    float acc[2][4][4];
    #pragma unroll
    for (int a = 0; a < 2; a++)
        #pragma unroll
        for (int b = 0; b < 4; b++)
            #pragma unroll
            for (int c = 0; c < 4; c++) acc[a][b][c] = 0.f;

    for (int k0 = 0; k0 < K; k0 += BK) {
        // A tile: 128 rows x 32 halfs, direct uint4 copies (8 halfs each)
        #pragma unroll
        for (int i = 0; i < 2; i++) {
            int f = tid + i * 256;
            int r = f >> 2, q = f & 3;
            int m = rowBase + r;
            uint4 u = make_uint4(0u, 0u, 0u, 0u);
            if (m < M) u = *(const uint4*)(A + (size_t)m * K + k0 + q * 8);
            *(uint4*)&sA[r * LDH + q * 8] = u;
        }
        // B tile: sB[n][k] = W2[k0+k][n], half2 over k pair
        #pragma unroll
        for (int i = 0; i < 4; i++) {
            int f = tid + i * 256;
            int n = f & (BN - 1), kp = f >> 6;     // kp: 0..15
            float w0 = W[(size_t)(k0 + 2 * kp) * BN + n];
            float w1 = W[(size_t)(k0 + 2 * kp + 1) * BN + n];
            *(__half2*)&sB[n * LDH + 2 * kp] = __floats2half2_rn(w0, w1);
        }
        __syncthreads();

        #pragma unroll
        for (int ks = 0; ks < 2; ks++) {
            uint32_t af[2][4];
            #pragma unroll
            for (int mt = 0; mt < 2; mt++) {
                uint32_t addr = sA_u +
                    ((warpM + mt * 16 + a_row) * LDH + ks * 16 + a_koff) * 2;
                asm volatile(
                    "ldmatrix.sync.aligned.m8n8.x4.shared.b16 {%0,%1,%2,%3}, [%4];"
                    : "=r"(af[mt][0]), "=r"(af[mt][1]),
                      "=r"(af[mt][2]), "=r"(af[mt][3])
                    : "r"(addr));
            }
            uint32_t bf[2][4];
            #pragma unroll
            for (int ntp = 0; ntp < 2; ntp++) {
                uint32_t addr = sB_u +
                    ((warpN + ntp * 16 + b_n) * LDH + ks * 16 + b_koff) * 2;
                asm volatile(
                    "ldmatrix.sync.aligned.m8n8.x4.shared.b16 {%0,%1,%2,%3}, [%4];"
                    : "=r"(bf[ntp][0]), "=r"(bf[ntp][1]),
                      "=r"(bf[ntp][2]), "=r"(bf[ntp][3])
                    : "r"(addr));
            }
            #pragma unroll
            for (int mt = 0; mt < 2; mt++)
                #pragma unroll
                for (int ntp = 0; ntp < 2; ntp++)
                    #pragma unroll
                    for (int hh = 0; hh < 2; hh++) {
                        int nt = ntp * 2 + hh;
                        asm volatile(
                            "mma.sync.aligned.m16n8k16.row.col.f32.f16.f16.f32 "
                            "{%0,%1,%2,%3}, {%4,%5,%6,%7}, {%8,%9}, {%0,%1,%2,%3};"
                            : "+f"(acc[mt][nt][0]), "+f"(acc[mt][nt][1]),
                              "+f"(acc[mt][nt][2]), "+f"(acc[mt][nt][3])
                            : "r"(af[mt][0]), "r"(af[mt][1]),
                              "r"(af[mt][2]), "r"(af[mt][3]),
                              "r"(bf[ntp][hh * 2 + 0]), "r"(bf[ntp][hh * 2 + 1]));
                    }
        }
        __syncthreads();
    }

    #pragma unroll
    for (int mt = 0; mt < 2; mt++)
        #pragma unroll
        for (int rr = 0; rr < 2; rr++) {
            int m = rowBase + warpM + mt * 16 + rr * 8 + gid;
            if (m < M) {
                __half* cp = C + (size_t)m * BN + warpN;
                #pragma unroll
                for (int nt = 0; nt < 4; nt++)
                    *(__half2*)(cp + nt * 8 + 2 * tig) =
                        __floats2half2_rn(acc[mt][nt][rr * 2 + 0],
                                          acc[mt][nt][rr * 2 + 1]);
            }
        }
}

// ---------------------------------------------------------------------------
// CSR build
// ---------------------------------------------------------------------------
__global__ void zero_counts_kernel(int* __restrict__ cnt, int n) {
    int i = blockIdx.x * blockDim.x + threadIdx.x;
    if (i < n) cnt[i] = 0;
}

__global__ void hist_kernel(const int* __restrict__ rows, int* __restrict__ cnt, int E) {
    int e = blockIdx.x * blockDim.x + threadIdx.x;
    if (e < E) atomicAdd(&cnt[rows[e]], 1);
}

__global__ __launch_bounds__(1024) void scan_kernel(
        int* __restrict__ cnt_and_cursor, int* __restrict__ rowptr, int N, int E) {
    __shared__ int part[1024];
    const int t = threadIdx.x;
    const int chunk = (N + 1023) / 1024;
    const int lo = t * chunk;
    const int hi = min(lo + chunk, N);
    int s = 0;
    for (int i = lo; i < hi; i++) s += cnt_and_cursor[i];
    part[t] = s;
    __syncthreads();
    #pragma unroll
    for (int off = 1; off < 1024; off <<= 1) {
        int v = (t >= off) ? part[t - off] : 0;
        __syncthreads();
        part[t] += v;
        __syncthreads();
    }
    int base = (t == 0) ? 0 : part[t - 1];
    for (int i = lo; i < hi; i++) {
        int c = cnt_and_cursor[i];
        rowptr[i] = base;
        cnt_and_cursor[i] = base;
        base += c;
    }
    if (t == 0) rowptr[N] = E;
}

__global__ void scatter_kernel(const int* __restrict__ rows,
                               const int* __restrict__ cols,
                               const float* __restrict__ ew,
                               int* __restrict__ cursor,
                               int2* __restrict__ edges, int E) {
    int e = blockIdx.x * blockDim.x + threadIdx.x;
    if (e >= E) return;
    int r = rows[e];
    int pos = atomicAdd(&cursor[r], 1);
    edges[pos] = make_int2(cols[e], __float_as_int(ew[e]));
}

// ---------------------------------------------------------------------------
// SpMM1: warp per row, D=128 fp16 payload; dst = relu(bias + sum) in fp16.
// ---------------------------------------------------------------------------
__global__ void csr_spmm_h_relu_kernel(const int* __restrict__ rowptr,
                                       const int2* __restrict__ edges,
                                       const __half* __restrict__ src,
                                       const float* __restrict__ bias,
                                       __half* __restrict__ dst, int N) {
    constexpr int D = 128;
    const int lane = threadIdx.x & 31;
    const int row  = blockIdx.x * (blockDim.x >> 5) + (threadIdx.x >> 5);
    if (row >= N) return;

    const int s = rowptr[row];
    const int e = rowptr[row + 1];

    float acc[4];
    #pragma unroll
    for (int v = 0; v < 4; v++) acc[v] = bias[lane * 4 + v];

    int j = s;
    for (; j + 2 <= e; j += 2) {
        int2 e0 = edges[j], e1 = edges[j + 1];
        float w0 = __int_as_float(e0.y), w1 = __int_as_float(e1.y);
        uint2 u0 = *(const uint2*)(src + (size_t)e0.x * D + lane * 4);
        uint2 u1 = *(const uint2*)(src + (size_t)e1.x * D + lane * 4);
        float2 a0 = __half22float2(*(const __half2*)&u0.x);
        float2 a1 = __half22float2(*(const __half2*)&u0.y);
        float2 c0 = __half22float2(*(const __half2*)&u1.x);
        float2 c1 = __half22float2(*(const __half2*)&u1.y);
        acc[0] = fmaf(w0, a0.x, fmaf(w1, c0.x, acc[0]));
        acc[1] = fmaf(w0, a0.y, fmaf(w1, c0.y, acc[1]));
        acc[2] = fmaf(w0, a1.x, fmaf(w1, c1.x, acc[2]));
        acc[3] = fmaf(w0, a1.y, fmaf(w1, c1.y, acc[3]));
    }
    if (j < e) {
        int2 e0 = edges[j];
        float w0 = __int_as_float(e0.y);
        uint2 u0 = *(const uint2*)(src + (size_t)e0.x * D + lane * 4);
        float2 a0 = __half22float2(*(const __half2*)&u0.x);
        float2 a1 = __half22float2(*(const __half2*)&u0.y);
        acc[0] = fmaf(w0, a0.x, acc[0]);
        acc[1] = fmaf(w0, a0.y, acc[1]);
        acc[2] = fmaf(w0, a1.x, acc[2]);
        acc[3] = fmaf(w0, a1.y, acc[3]);
    }

    #pragma unroll
    for (int v = 0; v < 4; v++) acc[v] = fmaxf(acc[v], 0.f);
    __half2 h0 = __floats2half2_rn(acc[0], acc[1]);
    __half2 h1 = __floats2half2_rn(acc[2], acc[3]);
    uint2 u;
    u.x = *(uint32_t*)&h0; u.y = *(uint32_t*)&h1;
    *(uint2*)(dst + (size_t)row * D + lane * 4) = u;
}

// ---------------------------------------------------------------------------
// SpMM2: warp per row, D=64 fp16 payload; dst = bias + sum in fp32.
// ---------------------------------------------------------------------------
__global__ void csr_spmm_h_f_kernel(const int* __restrict__ rowptr,
                                    const int2* __restrict__ edges,
                                    const __half* __restrict__ src,
                                    const float* __restrict__ bias,
                                    float* __restrict__ dst, int N) {
    constexpr int D = 64;
    const int lane = threadIdx.x & 31;
    const int row  = blockIdx.x * (blockDim.x >> 5) + (threadIdx.x >> 5);
    if (row >= N) return;

    const int s = rowptr[row];
    const int e = rowptr[row + 1];

    float acc[2];
    acc[0] = bias[lane * 2 + 0];
    acc[1] = bias[lane * 2 + 1];

    int j = s;
    for (; j + 2 <= e; j += 2) {
        int2 e0 = edges[j], e1 = edges[j + 1];
        float w0 = __int_as_float(e0.y), w1 = __int_as_float(e1.y);
        float2 a0 = __half22float2(*(const __half2*)(src + (size_t)e0.x * D + lane * 2));
        float2 c0 = __half22float2(*(const __half2*)(src + (size_t)e1.x * D + lane * 2));
        acc[0] = fmaf(w0, a0.x, fmaf(w1, c0.x, acc[0]));
        acc[1] = fmaf(w0, a0.y, fmaf(w1, c0.y, acc[1]));
    }
    if (j < e) {
        int2 e0 = edges[j];
        float w0 = __int_as_float(e0.y);
        float2 a0 = __half22float2(*(const __half2*)(src + (size_t)e0.x * D + lane * 2));
        acc[0] = fmaf(w0, a0.x, acc[0]);
        acc[1] = fmaf(w0, a0.y, acc[1]);
    }

    *(float2*)(dst + (size_t)row * D + lane * 2) = make_float2(acc[0], acc[1]);
}

// ---------------------------------------------------------------------------
extern "C" void kernel_launch(void* const* d_in, const int* in_sizes, int n_in,
                              void* d_out, int out_size) {
    const float* x  = (const float*)d_in[0];
    const int*   ei = (const int*)d_in[1];     // [2, E] int32
    const float* ew = (const float*)d_in[2];
    const float* W1 = (const float*)d_in[3];
    const float* b1 = (const float*)d_in[4];
    const float* W2 = (const float*)d_in[5];
    const float* b2 = (const float*)d_in[6];
    float* out = (float*)d_out;

    const int M = in_sizes[0] / IN_DIM;   // 50000
    const int E = in_sizes[2];            // 1600000

    __half *S1, *H, *S2;
    int *rowptr, *rowaux;
    int2 *edges;
    cudaGetSymbolAddress((void**)&S1, g_S1);
    cudaGetSymbolAddress((void**)&H,  g_H);
    cudaGetSymbolAddress((void**)&S2, g_S2);
    cudaGetSymbolAddress((void**)&rowptr, g_rowptr);
    cudaGetSymbolAddress((void**)&rowaux, g_rowaux);
    cudaGetSymbolAddress((void**)&edges,  g_edges);

    const int* e_rows = ei;
    const int* e_cols = ei + E;

    static cudaStream_t s_build = nullptr;
    static cudaEvent_t  ev_fork = nullptr, ev_join = nullptr;
    if (s_build == nullptr) {
        cudaStreamCreateWithFlags(&s_build, cudaStreamNonBlocking);
        cudaEventCreateWithFlags(&ev_fork, cudaEventDisableTiming);
        cudaEventCreateWithFlags(&ev_join, cudaEventDisableTiming);
    }

    // ---- fork: CSR build on side stream, GEMM1 on main ----
    cudaEventRecord(ev_fork, 0);
    cudaStreamWaitEvent(s_build, ev_fork, 0);

    zero_counts_kernel<<<(M + 255) / 256, 256, 0, s_build>>>(rowaux, M);
    hist_kernel<<<(E + 255) / 256, 256, 0, s_build>>>(e_rows, rowaux, E);
    scan_kernel<<<1, 1024, 0, s_build>>>(rowaux, rowptr, M, E);
    scatter_kernel<<<(E + 255) / 256, 256, 0, s_build>>>(e_rows, e_cols, ew,
                                                         rowaux, edges, E);
    cudaEventRecord(ev_join, s_build);

    // GEMM1: S1 = x @ W1 (fp16 mma) — concurrent with CSR build
    gemm1_mma_f16<<<(M + 127) / 128, 256>>>(x, W1, S1, M);

    // ---- join ----
    cudaStreamWaitEvent(0, ev_join, 0);

    // SpMM1: H = relu(A @ S1 + b1), fp16 out
    csr_spmm_h_relu_kernel<<<(M + 7) / 8, 256>>>(rowptr, edges, S1, b1, H, M);

    // GEMM2: S2 = H @ W2 (fp16 mma)
    gemm2_mma_f16<<<(M + 127) / 128, 256>>>(H, W2, S2, M);

    // SpMM2: out = A @ S2 + b2 (fp32 out)
    csr_spmm_h_f_kernel<<<(M + 7) / 8, 256>>>(rowptr, edges, S2, b2, out, M);
}